// round 15
// baseline (speedup 1.0000x reference)
#include <cuda_runtime.h>
#include <cuda_bf16.h>

// SAR-ADC true-quantization: x[500000,24] f32, W[10] f32 ->
//   q[500000,24] f32  (first 12,000,000 floats of d_out)
//   Q[500000,24,4] f32 (next 48,000,000 floats of d_out)
//
// R14: 4-way stride split. Thread t handles i, i+N/4, i+N/2, i+3N/4:
//  - 4 front-batched LDG.32 (MLP=4), 4 independent SAR chains (ILP=4)
//  - every load/store instruction keeps perfect lane coalescing
//    (x/q: 4B lane stride; Q: STG.128 with 16B lane stride = 512B/warp)
//  - sign(v + 1e-30) == (v >= 0 ? +1 : -1) exactly in fp32 for this data.

#define LENGTH_ 500000
#define NADC_   24
#define NTOT_   (LENGTH_ * NADC_)    // 12,000,000
#define QTR_    (NTOT_ / 4)          // 3,000,000

__global__ __launch_bounds__(256)
void sar_quant_kernel(const float* __restrict__ x,
                      const float* __restrict__ W,
                      float* __restrict__ q,
                      float4* __restrict__ Qout) {
    int i = blockIdx.x * blockDim.x + threadIdx.x;
    if (i >= QTR_) return;

    int idx[4] = { i, i + QTR_, i + 2 * QTR_, i + 3 * QTR_ };

    // Front-batch all 4 input loads (independent, MLP=4).
    float xv[4];
    #pragma unroll
    for (int g = 0; g < 4; g++) xv[g] = x[idx[g]];

    // Vectorized weight load: 3 broadcast LDGs.
    const float4 wA = __ldg((const float4*)W);       // W[0..3]
    const float4 wB = __ldg(((const float4*)W) + 1); // W[4..7]
    const float2 wC = __ldg((const float2*)(W + 8)); // W[8..9]

    const float VR = 1.8f / 16.0f;   // LSB voltage; VREF == VR
    // Weight walk m = 9..0, scaled by VR. b_k carries the 0.5 of (Q+1)/2.
    const float t3  = wC.y * VR;   // W[9]
    const float t2  = wC.x * VR;   // W[8]
    const float c23 = wB.w * VR;   // W[7]
    const float t1  = wB.z * VR;   // W[6]
    const float c12 = wB.y * VR;   // W[5]
    const float c13 = wB.x * VR;   // W[4]
    const float t0  = wA.w * VR;   // W[3]
    const float c01 = wA.z * VR;   // W[2]
    const float c02 = wA.y * VR;   // W[1]
    const float c03 = wA.x * VR;   // W[0]

    float  qv[4];
    float4 Qv[4];

    #pragma unroll
    for (int g = 0; g < 4; g++) {
        float xx = xv[g];

        bool p3 = (xx - t3) >= 0.0f;
        float b3 = p3 ? 1.0f : 0.0f;
        bool p2 = (xx - (t2 + b3 * c23)) >= 0.0f;
        float b2 = p2 ? 1.0f : 0.0f;
        bool p1 = (xx - (t1 + b2 * c12 + b3 * c13)) >= 0.0f;
        float b1 = p1 ? 1.0f : 0.0f;
        bool p0 = (xx - (t0 + b1 * c01 + b2 * c02 + b3 * c03)) >= 0.0f;
        float b0 = p0 ? 1.0f : 0.0f;

        qv[g] = VR * (b0 + 2.0f * b1 + 4.0f * b2 + 8.0f * b3);
        Qv[g] = make_float4(p0 ? 1.0f : -1.0f,
                            p1 ? 1.0f : -1.0f,
                            p2 ? 1.0f : -1.0f,
                            p3 ? 1.0f : -1.0f);
    }

    #pragma unroll
    for (int g = 0; g < 4; g++) q[idx[g]] = qv[g];
    #pragma unroll
    for (int g = 0; g < 4; g++) Qout[idx[g]] = Qv[g];
}

extern "C" void kernel_launch(void* const* d_in, const int* in_sizes, int n_in,
                              void* d_out, int out_size) {
    const float* x = (const float*)d_in[0];
    const float* W = (const float*)d_in[1];
    float* out = (float*)d_out;
    float*  q    = out;                              // 12,000,000 floats
    float4* Qout = (float4*)(out + (size_t)NTOT_);   // 48,000,000 floats

    const int threads = 256;
    const int blocks  = (QTR_ + threads - 1) / threads;
    sar_quant_kernel<<<blocks, threads>>>(x, W, q, Qout);
}